// round 8
// baseline (speedup 1.0000x reference)
#include <cuda_runtime.h>

// ---------------- problem constants ----------------
#define KDIM 128          // feature / hidden / out dim
#define TM   128          // edges (rows) per CTA tile
#define SA   132          // padded smem stride (floats)
#define NTHREADS 256
#define MAX_NODES 100000

// ---------------- device scratch (no cudaMalloc allowed) ----------------
__device__ float g_wT[4][KDIM * KDIM];            // k-major weights: 0=w_efeat,1=w_src,2=w_dst,3=w2
__device__ float g_proj[2][MAX_NODES * KDIM];     // 0 = mlp_src, 1 = mlp_dst(+b1)

typedef unsigned long long u64;

// ---------------- f32x2 packed helpers (Blackwell sm_103a) ----------------
__device__ __forceinline__ u64 dup2(float x) {
    u64 r; asm("mov.b64 %0,{%1,%1};" : "=l"(r) : "f"(x)); return r;
}
__device__ __forceinline__ void fma2(u64 &d, u64 a, u64 b) {
    asm("fma.rn.f32x2 %0,%1,%2,%0;" : "+l"(d) : "l"(a), "l"(b));
}
__device__ __forceinline__ float2 upk(u64 v) {
    float2 f; asm("mov.b64 {%0,%1},%2;" : "=f"(f.x), "=f"(f.y) : "l"(v)); return f;
}

// ---------------- weight pre-transpose: g_wT[b][k*128+n] = w[n*128+k] ----------------
__global__ void wtranspose_kernel(const float* __restrict__ w0, const float* __restrict__ w1,
                                  const float* __restrict__ w2_, const float* __restrict__ w3) {
    const float* src = (blockIdx.x == 0) ? w0 : (blockIdx.x == 1) ? w1 : (blockIdx.x == 2) ? w2_ : w3;
    float* dst = g_wT[blockIdx.x];
    for (int v = threadIdx.x; v < KDIM * KDIM; v += blockDim.x) {
        int k = v & (KDIM - 1);
        int n = v >> 7;
        dst[k * KDIM + n] = src[n * KDIM + k];
    }
}

// ---------------- smem loaders ----------------
// Load a [TM x 128] row-major tile transposed into As[k][m] (stride SA), zero-pad OOB rows.
__device__ __forceinline__ void load_A_transposed(float* As, const float* __restrict__ feat,
                                                  int base, int limit, int t) {
    int lane = t & 31, warp = t >> 5;
    int q  = lane >> 3;   // 0..3  (row offset)
    int kc = lane & 7;    // 0..7  (float4 chunk within 8)
#pragma unroll
    for (int i = 0; i < 16; i++) {
        int m     = q + 4 * warp + 32 * (i & 3);   // 0..127
        int chunk = kc + 8 * (i >> 2);             // 0..31
        int row   = base + m;
        float4 v = make_float4(0.f, 0.f, 0.f, 0.f);
        if (row < limit)
            v = *(const float4*)(feat + (size_t)row * KDIM + chunk * 4);
        int k = chunk * 4;
        As[(k + 0) * SA + m] = v.x;
        As[(k + 1) * SA + m] = v.y;
        As[(k + 2) * SA + m] = v.z;
        As[(k + 3) * SA + m] = v.w;
    }
}

// Copy pre-transposed weights (dense, stride 128) into padded smem (stride SA).
__device__ __forceinline__ void copy_B(float* Bs, const float* __restrict__ wT, int t) {
#pragma unroll
    for (int i = 0; i < 16; i++) {
        int v = t + i * NTHREADS;
        int k = v >> 5;
        int n = (v & 31) * 4;
        *(float4*)(Bs + k * SA + n) = *(const float4*)(wT + k * KDIM + n);
    }
}

// ---------------- core GEMM: acc[m][n] += sum_k As[k][m] * Bs[k][n], 8x8 per thread ----------------
__device__ __forceinline__ void gemm128(const float* As, const float* Bs,
                                        u64 acc[32], int row0, int col0) {
#pragma unroll 2
    for (int k = 0; k < KDIM; k++) {
        const float* ap = As + k * SA + row0;
        float4 a0 = *(const float4*)ap;
        float4 a1 = *(const float4*)(ap + 4);
        const u64* bp = (const u64*)(Bs + k * SA + col0);
        u64 b0 = bp[0], b1 = bp[1], b2 = bp[2], b3 = bp[3];
        float a[8] = {a0.x, a0.y, a0.z, a0.w, a1.x, a1.y, a1.z, a1.w};
#pragma unroll
        for (int r = 0; r < 8; r++) {
            u64 ad = dup2(a[r]);
            fma2(acc[r * 4 + 0], ad, b0);
            fma2(acc[r * 4 + 1], ad, b1);
            fma2(acc[r * 4 + 2], ad, b2);
            fma2(acc[r * 4 + 3], ad, b3);
        }
    }
}

// ---------------- node projection kernel: g_proj[which] = feat @ wT (+bias) ----------------
__global__ void __launch_bounds__(NTHREADS, 1)
node_kernel(const float* __restrict__ feat, const float* __restrict__ bias,
            int N, int which, int wsel) {
    extern __shared__ float sm[];
    float* As = sm;
    float* Bs = sm + KDIM * SA;
    int t = threadIdx.x;
    int n0 = blockIdx.x * TM;

    load_A_transposed(As, feat, n0, N, t);
    copy_B(Bs, g_wT[wsel], t);
    __syncthreads();

    int tx = t & 15, ty = t >> 4;
    int row0 = ty * 8, col0 = tx * 8;

    u64 acc[32];
#pragma unroll
    for (int i = 0; i < 32; i++) acc[i] = 0ull;
    gemm128(As, Bs, acc, row0, col0);

    float bb[8];
#pragma unroll
    for (int c = 0; c < 8; c++) bb[c] = bias ? __ldg(bias + col0 + c) : 0.f;

    float* outp = g_proj[which];
#pragma unroll
    for (int r = 0; r < 8; r++) {
        int m = n0 + row0 + r;
        if (m < N) {
            float o[8];
#pragma unroll
            for (int c2 = 0; c2 < 4; c2++) {
                float2 f = upk(acc[r * 4 + c2]);
                o[c2 * 2 + 0] = f.x + bb[c2 * 2 + 0];
                o[c2 * 2 + 1] = f.y + bb[c2 * 2 + 1];
            }
            float* po = outp + (size_t)m * KDIM + col0;
            *(float4*)(po + 0) = make_float4(o[0], o[1], o[2], o[3]);
            *(float4*)(po + 4) = make_float4(o[4], o[5], o[6], o[7]);
        }
    }
}

// ---------------- fused edge kernel: GEMM1 + gather + SiLU + GEMM2 + LayerNorm ----------------
__global__ void __launch_bounds__(NTHREADS, 1)
edge_kernel(const float* __restrict__ efeat,
            const int* __restrict__ srcidx, const int* __restrict__ dstidx,
            const float* __restrict__ b2, const float* __restrict__ gamma,
            const float* __restrict__ beta,
            float* __restrict__ out, int E) {
    extern __shared__ float sm[];
    float* As  = sm;
    float* Bs1 = sm + 1 * KDIM * SA;
    float* Bs2 = sm + 2 * KDIM * SA;
    float* tail = sm + 3 * KDIM * SA;
    int*   sidx = (int*)tail;
    int*   didx = sidx + TM;
    float* b2s  = (float*)(didx + TM);
    float* gs   = b2s + KDIM;
    float* bts  = gs + KDIM;

    int t = threadIdx.x;
    int e0 = blockIdx.x * TM;

    load_A_transposed(As, efeat, e0, E, t);
    copy_B(Bs1, g_wT[0], t);
    copy_B(Bs2, g_wT[3], t);
    if (t < TM) {
        int e = e0 + t;
        sidx[t] = (e < E) ? srcidx[e] : 0;
        didx[t] = (e < E) ? dstidx[e] : 0;
    } else {
        int c = t - TM;   // 0..127
        b2s[c] = b2[c];
        gs[c]  = gamma[c];
        bts[c] = beta[c];
    }
    __syncthreads();

    int tx = t & 15, ty = t >> 4;
    int row0 = ty * 8, col0 = tx * 8;

    // ---- GEMM1: mlp_efeat tile ----
    u64 acc[32];
#pragma unroll
    for (int i = 0; i < 32; i++) acc[i] = 0ull;
    gemm128(As, Bs1, acc, row0, col0);
    __syncthreads();   // all reads of As done before overwrite

    // ---- epilogue 1: + gathered node projections, SiLU, write transposed into As ----
    const float* srcp = g_proj[0];
    const float* dstp = g_proj[1];
    float y[8][8];
#pragma unroll
    for (int r = 0; r < 8; r++) {
        int is = sidx[row0 + r], id = didx[row0 + r];
        const float* ps = srcp + (size_t)is * KDIM + col0;
        const float* pd = dstp + (size_t)id * KDIM + col0;
        float4 s0 = *(const float4*)ps,       s1 = *(const float4*)(ps + 4);
        float4 d0 = *(const float4*)pd,       d1 = *(const float4*)(pd + 4);
        float g[8] = {s0.x + d0.x, s0.y + d0.y, s0.z + d0.z, s0.w + d0.w,
                      s1.x + d1.x, s1.y + d1.y, s1.z + d1.z, s1.w + d1.w};
#pragma unroll
        for (int c2 = 0; c2 < 4; c2++) {
            float2 f = upk(acc[r * 4 + c2]);
            float x0 = f.x + g[c2 * 2 + 0];
            float x1 = f.y + g[c2 * 2 + 1];
            y[r][c2 * 2 + 0] = x0 * __fdividef(1.f, 1.f + __expf(-x0));
            y[r][c2 * 2 + 1] = x1 * __fdividef(1.f, 1.f + __expf(-x1));
        }
    }
    // s tile transposed: As[k = GEMM1 col][m = edge row]
#pragma unroll
    for (int c = 0; c < 8; c++) {
        *(float4*)(As + (col0 + c) * SA + row0 + 0) = make_float4(y[0][c], y[1][c], y[2][c], y[3][c]);
        *(float4*)(As + (col0 + c) * SA + row0 + 4) = make_float4(y[4][c], y[5][c], y[6][c], y[7][c]);
    }
    __syncthreads();

    // ---- GEMM2: h = silu(sum) @ w2^T ----
#pragma unroll
    for (int i = 0; i < 32; i++) acc[i] = 0ull;
    gemm128(As, Bs2, acc, row0, col0);

    // ---- epilogue 2: +b2, LayerNorm over 128 (16 lanes share a row), store ----
#pragma unroll
    for (int r = 0; r < 8; r++) {
        float h[8];
#pragma unroll
        for (int c2 = 0; c2 < 4; c2++) {
            float2 f = upk(acc[r * 4 + c2]);
            h[c2 * 2 + 0] = f.x + b2s[col0 + c2 * 2 + 0];
            h[c2 * 2 + 1] = f.y + b2s[col0 + c2 * 2 + 1];
        }
        float s = 0.f, ss = 0.f;
#pragma unroll
        for (int c = 0; c < 8; c++) { s += h[c]; ss += h[c] * h[c]; }
#pragma unroll
        for (int m = 8; m >= 1; m >>= 1) {
            s  += __shfl_xor_sync(0xffffffffu, s,  m);
            ss += __shfl_xor_sync(0xffffffffu, ss, m);
        }
        float mu   = s * (1.f / 128.f);
        float var  = ss * (1.f / 128.f) - mu * mu;
        float rstd = rsqrtf(var + 1e-5f);
        int e = e0 + row0 + r;
        if (e < E) {
            float o[8];
#pragma unroll
            for (int c = 0; c < 8; c++)
                o[c] = (h[c] - mu) * rstd * gs[col0 + c] + bts[col0 + c];
            float* po = out + (size_t)e * KDIM + col0;
            *(float4*)(po + 0) = make_float4(o[0], o[1], o[2], o[3]);
            *(float4*)(po + 4) = make_float4(o[4], o[5], o[6], o[7]);
        }
    }
}

// ---------------- launch ----------------
extern "C" void kernel_launch(void* const* d_in, const int* in_sizes, int n_in,
                              void* d_out, int out_size) {
    const float* efeat    = (const float*)d_in[0];
    const float* src_feat = (const float*)d_in[1];
    const float* dst_feat = (const float*)d_in[2];
    const int*   src_idx  = (const int*)  d_in[3];
    const int*   dst_idx  = (const int*)  d_in[4];
    const float* w_efeat  = (const float*)d_in[5];
    const float* w_src    = (const float*)d_in[6];
    const float* w_dst    = (const float*)d_in[7];
    const float* b1       = (const float*)d_in[8];
    const float* w2       = (const float*)d_in[9];
    const float* b2       = (const float*)d_in[10];
    const float* ln_gamma = (const float*)d_in[11];
    const float* ln_beta  = (const float*)d_in[12];
    float* out = (float*)d_out;

    int E = in_sizes[3];           // src_idx element count
    int N = in_sizes[1] / KDIM;    // node count

    const int node_smem = 2 * KDIM * SA * (int)sizeof(float);                       // 135168 B
    const int edge_smem = (3 * KDIM * SA + 2 * TM + 3 * KDIM) * (int)sizeof(float); // 205312 B
    cudaFuncSetAttribute(node_kernel, cudaFuncAttributeMaxDynamicSharedMemorySize, node_smem);
    cudaFuncSetAttribute(edge_kernel, cudaFuncAttributeMaxDynamicSharedMemorySize, edge_smem);

    // 1) weights -> k-major
    wtranspose_kernel<<<4, 256>>>(w_efeat, w_src, w_dst, w2);

    // 2) node projections (bias b1 folded into dst branch, as in reference)
    int node_grid = (N + TM - 1) / TM;
    node_kernel<<<node_grid, NTHREADS, node_smem>>>(src_feat, nullptr, N, 0, 1);
    node_kernel<<<node_grid, NTHREADS, node_smem>>>(dst_feat, b1,      N, 1, 2);

    // 3) fused edge pipeline
    int edge_grid = (E + TM - 1) / TM;
    edge_kernel<<<edge_grid, NTHREADS, edge_smem>>>(efeat, src_idx, dst_idx,
                                                    b2, ln_gamma, ln_beta, out, E);
}